// round 12
// baseline (speedup 1.0000x reference)
#include <cuda_runtime.h>
#include <cuda_fp16.h>
#include <mma.h>
#include <math.h>

using namespace nvcuda;

#define NN 100000
#define EE 1600000

// ---------------- device scratch (no allocations allowed) ----------------
__device__ int   g_count[NN];
__device__ int   g_rowptr[NN + 1];
__device__ int   g_cursor[NN];
__device__ float g_dinv[NN];
__device__ int2  g_epack[EE];              // (src, norm bits)
__device__ __half g_hlin[NN * 64];         // fp16 GCN linear output
__device__ float g_h[NN * 64];             // fp32 residual stream
__device__ __half g_h16[NN * 64];          // fp16 copy of final h for GAT gathers
__device__ __half g_hagg[NN * 256];        // fp16 per-head aggregated h
__device__ float g_asrc[NN * 4];
__device__ float g_adst[NN * 4];
__device__ float g_Wa[64 * 8];             // composite att weights
__device__ __half g_Wcomb16[256 * 64];     // folded wg.wc1 (fp16)
__device__ float g_const[64];              // folded bc1 + bg.wc1

// Inline dtype check: int64 ids < 2^31 => odd int32 words all zero.
__device__ __forceinline__ int detect64(const int* p) {
    int is64 = 1;
#pragma unroll
    for (int i = 1; i < 32; i += 2)
        if (p[i] != 0) is64 = 0;
    return is64;
}

__device__ __forceinline__ int ld_edge(const void* ei, int is64, long long idx) {
    if (is64) return (int)((const long long*)ei)[idx];
    return ((const int*)ei)[idx];
}

// ---------------- CSR build ----------------
__global__ void k_zero(int n) {
    int i = blockIdx.x * blockDim.x + threadIdx.x;
    if (i < n) g_count[i] = 0;
}

__global__ void k_count(const void* __restrict__ ei, int e) {
    int i = blockIdx.x * blockDim.x + threadIdx.x;
    if (i < e) {
        int is64 = detect64((const int*)ei);
        int d = ld_edge(ei, is64, (long long)e + i);
        atomicAdd(&g_count[d], 1);
    }
}

// single-block tiled scan over g_count: rowptr/cursor/dinv in one launch
__global__ void __launch_bounds__(1024) k_scanall(int n, int e) {
    __shared__ int warpsum[32];
    __shared__ int s_running;
    int tid = threadIdx.x, lane = tid & 31, wid = tid >> 5;
    if (tid == 0) s_running = 0;
    __syncthreads();
    int tiles = (n + 1023) >> 10;
    for (int tIdx = 0; tIdx < tiles; ++tIdx) {
        int i = (tIdx << 10) + tid;
        int v = (i < n) ? g_count[i] : 0;
        int x = v;
#pragma unroll
        for (int off = 1; off < 32; off <<= 1) {
            int y = __shfl_up_sync(0xffffffffu, x, off);
            if (lane >= off) x += y;
        }
        if (lane == 31) warpsum[wid] = x;
        __syncthreads();
        if (wid == 0) {
            int w = warpsum[lane];
#pragma unroll
            for (int off = 1; off < 32; off <<= 1) {
                int y = __shfl_up_sync(0xffffffffu, w, off);
                if (lane >= off) w += y;
            }
            warpsum[lane] = w;
        }
        __syncthreads();
        int warpoff = (wid == 0) ? 0 : warpsum[wid - 1];
        int excl = s_running + warpoff + x - v;
        if (i < n) {
            g_rowptr[i] = excl;
            g_cursor[i] = excl;
            g_dinv[i] = rsqrtf((float)(v + 1));
        }
        __syncthreads();
        if (tid == 0) s_running += warpsum[31];
        __syncthreads();
    }
    if (tid == 0) g_rowptr[n] = e;
}

__global__ void k_scatter(const void* __restrict__ ei, int e) {
    int i = blockIdx.x * blockDim.x + threadIdx.x;
    if (i < e) {
        int is64 = detect64((const int*)ei);
        int s = ld_edge(ei, is64, i);
        int d = ld_edge(ei, is64, (long long)e + i);
        int p = atomicAdd(&g_cursor[d], 1);
        g_epack[p] = make_int2(s, __float_as_int(g_dinv[s] * g_dinv[d]));
    }
}

// ---------------- layer-1 GEMM: hlin = X[N,8] @ W[8,64] (fp16 out) ----------------
__global__ void k_gemm8(const float* __restrict__ X, const float* __restrict__ W, int n) {
    __shared__ float sx[4][8];
    int tid = threadIdx.x;
    int l = tid >> 6, col = tid & 63;
    int base = blockIdx.x * 4;
    if (tid < 32) {
        int r = base + (tid >> 3);
        sx[tid >> 3][tid & 7] = (r < n) ? X[r * 8 + (tid & 7)] : 0.f;
    }
    __syncthreads();
    int node = base + l;
    if (node < n) {
        float acc = 0.f;
#pragma unroll
        for (int k = 0; k < 8; ++k) acc += sx[l][k] * W[k * 64 + col];
        g_hlin[node * 64 + col] = __float2half(acc);
    }
}

// ---------------- GCN GEMM: hlin = g_h @ W[64,64], scalar W col in regs ----------------
__global__ void __launch_bounds__(256) k_gemm64(const float* __restrict__ W, int n) {
    float w[64];
    int tid = threadIdx.x;
    int l = tid >> 6, col = tid & 63;
#pragma unroll
    for (int k = 0; k < 64; ++k) w[k] = W[k * 64 + col];
    __shared__ float sx[4][64];
    for (int base = blockIdx.x * 4; base < n; base += gridDim.x * 4) {
        __syncthreads();
        int r = base + (tid >> 6);
        sx[tid >> 6][tid & 63] = (r < n) ? g_h[r * 64 + (tid & 63)] : 0.f;
        __syncthreads();
        int node = base + l;
        if (node < n) {
            float acc = 0.f;
#pragma unroll
            for (int k = 0; k < 64; ++k) acc += sx[l][k] * w[k];
            g_hlin[node * 64 + col] = __float2half(acc);
        }
    }
}

// ---------------- GCN aggregation: warp/node, fp16 gathers, 8-deep prefetch ----------------
__global__ void k_gcn_agg(const float* __restrict__ b, int n, int residual) {
    int tid = threadIdx.x, warp = tid >> 5, lane = tid & 31;
    int node = blockIdx.x * 8 + warp;
    if (node >= n) return;
    float di = g_dinv[node];
    float2 self = __half22float2(*(const __half2*)&g_hlin[node * 64 + 2 * lane]);
    float accx = di * di * self.x, accy = di * di * self.y;
    int beg = g_rowptr[node], end = g_rowptr[node + 1];
    int j = beg;
    for (; j + 7 < end; j += 8) {
        int2 ep[8];
#pragma unroll
        for (int q = 0; q < 8; ++q) ep[q] = g_epack[j + q];
#pragma unroll
        for (int q = 0; q < 8; ++q) {
            float w = __int_as_float(ep[q].y);
            float2 v = __half22float2(*(const __half2*)&g_hlin[ep[q].x * 64 + 2 * lane]);
            accx += w * v.x; accy += w * v.y;
        }
    }
    for (; j < end; ++j) {
        int2 ep = g_epack[j];
        float w = __int_as_float(ep.y);
        float2 v = __half22float2(*(const __half2*)&g_hlin[ep.x * 64 + 2 * lane]);
        accx += w * v.x; accy += w * v.y;
    }
    float2 bb = ((const float2*)b)[lane];
    float vx = fmaxf(accx + bb.x, 0.f), vy = fmaxf(accy + bb.y, 0.f);
    float2* H = (float2*)g_h;
    if (residual) {
        float2 p = H[node * 32 + lane];
        H[node * 32 + lane] = make_float2(p.x + vx, p.y + vy);
    } else {
        H[node * 32 + lane] = make_float2(vx, vy);
    }
}

// ---------------- composite attention weights: Wa = wg . att  (64x8) ----------------
__global__ void k_att_pre(const float* __restrict__ wg,
                          const float* __restrict__ att_s,
                          const float* __restrict__ att_d) {
    int t = threadIdx.x;
    int o = t & 7, k = t >> 3;
    int h = o & 3;
    const float* att = (o < 4) ? att_s : att_d;
    float s = 0.f;
#pragma unroll 8
    for (int c = 0; c < 64; ++c) s += wg[k * 256 + h * 64 + c] * att[h * 64 + c];
    g_Wa[k * 8 + o] = s;
}

// ---------------- folded classifier weights (fp16): Wcomb16 ----------------
__global__ void k_wcomb(const float* __restrict__ wg, const float* __restrict__ wc1) {
    int c = threadIdx.x;          // 64
    int hk = blockIdx.x;          // 256
    int h = hk >> 6, k = hk & 63;
    float s = 0.f;
#pragma unroll 8
    for (int j = 0; j < 64; ++j)
        s += wg[k * 256 + h * 64 + j] * wc1[(h * 64 + j) * 64 + c];
    g_Wcomb16[hk * 64 + c] = __float2half(s);
}

__global__ void k_const(const float* __restrict__ wc1, const float* __restrict__ bc1,
                        const float* __restrict__ bg) {
    int c = threadIdx.x;
    float s = bc1[c];
#pragma unroll 8
    for (int q = 0; q < 256; ++q) s += bg[q] * wc1[q * 64 + c];
    g_const[c] = s;
}

// ---------------- attention coeffs + fp16 h copy (warp per node) ----------------
__global__ void k_att(int n) {
    int tid = threadIdx.x, warp = tid >> 5, lane = tid & 31;
    int node = blockIdx.x * 8 + warp;
    if (node >= n) return;
    float2 hv = *(const float2*)&g_h[node * 64 + 2 * lane];
    ((__half2*)g_h16)[node * 32 + lane] = __floats2half2_rn(hv.x, hv.y);
    float r[8];
#pragma unroll
    for (int o = 0; o < 8; ++o) {
        r[o] = hv.x * g_Wa[(2 * lane) * 8 + o] + hv.y * g_Wa[(2 * lane + 1) * 8 + o];
#pragma unroll
        for (int off = 16; off > 0; off >>= 1)
            r[o] += __shfl_xor_sync(0xffffffffu, r[o], off);
    }
    if (lane < 4)      g_asrc[node * 4 + lane] = r[lane];
    else if (lane < 8) g_adst[node * 4 + lane - 4] = r[lane];
}

// ---------------- GAT softmax + 64-dim aggregation (linearity fold) ----------------
__device__ __forceinline__ float lrelu(float e) { return e > 0.f ? e : 0.2f * e; }

__device__ __forceinline__ float4 wmax4(float4 v) {
#pragma unroll
    for (int o = 16; o > 0; o >>= 1) {
        v.x = fmaxf(v.x, __shfl_xor_sync(0xffffffffu, v.x, o));
        v.y = fmaxf(v.y, __shfl_xor_sync(0xffffffffu, v.y, o));
        v.z = fmaxf(v.z, __shfl_xor_sync(0xffffffffu, v.z, o));
        v.w = fmaxf(v.w, __shfl_xor_sync(0xffffffffu, v.w, o));
    }
    return v;
}

__device__ __forceinline__ float4 wsum4(float4 v) {
#pragma unroll
    for (int o = 16; o > 0; o >>= 1) {
        v.x += __shfl_xor_sync(0xffffffffu, v.x, o);
        v.y += __shfl_xor_sync(0xffffffffu, v.y, o);
        v.z += __shfl_xor_sync(0xffffffffu, v.z, o);
        v.w += __shfl_xor_sync(0xffffffffu, v.w, o);
    }
    return v;
}

__global__ void __launch_bounds__(256) k_gat_agg2(int n) {
    int tid = threadIdx.x;
    int g = tid >> 6, t = tid & 63;
    int wig = (t >> 5) & 1;
    int lane = tid & 31;
    int node = blockIdx.x * 4 + g;
    bool valid = node < n;

    __shared__ float4 s_ex4[4][64];
    __shared__ int    s_srcv[4][64];
    __shared__ float4 s_red[4][2];
    __shared__ float2 s_part[4][4][32];
    __shared__ int    s_nt[4];

    int beg = 0, m = 0;
    if (valid) { beg = g_rowptr[node]; m = g_rowptr[node + 1] - beg + 1; }

    float4 ad = valid ? ((const float4*)g_adst)[node] : make_float4(0, 0, 0, 0);

    float4 mx = make_float4(-1e30f, -1e30f, -1e30f, -1e30f);
    for (int j = t; j < m; j += 64) {
        int s = (j < m - 1) ? g_epack[beg + j].x : node;
        float4 as = ((const float4*)g_asrc)[s];
        mx.x = fmaxf(mx.x, lrelu(as.x + ad.x));
        mx.y = fmaxf(mx.y, lrelu(as.y + ad.y));
        mx.z = fmaxf(mx.z, lrelu(as.z + ad.z));
        mx.w = fmaxf(mx.w, lrelu(as.w + ad.w));
    }
    mx = wmax4(mx);
    if (lane == 0) s_red[g][wig] = mx;
    if (t == 0) s_nt[g] = (m + 63) >> 6;
    __syncthreads();
    {
        float4 a = s_red[g][0], b2 = s_red[g][1];
        mx.x = fmaxf(a.x, b2.x); mx.y = fmaxf(a.y, b2.y);
        mx.z = fmaxf(a.z, b2.z); mx.w = fmaxf(a.w, b2.w);
    }
    int ntmax = max(max(s_nt[0], s_nt[1]), max(s_nt[2], s_nt[3]));

    float2 acc0 = make_float2(0, 0), acc1 = make_float2(0, 0);
    float2 acc2 = make_float2(0, 0), acc3 = make_float2(0, 0);
    float4 den = make_float4(0, 0, 0, 0);
    const __half2* h2p = (const __half2*)g_h16;

    for (int tile = 0; tile < ntmax; ++tile) {
        __syncthreads();
        int j = tile * 64 + t;
        if (j < m) {
            int s = (j < m - 1) ? g_epack[beg + j].x : node;
            s_srcv[g][t] = s;
            float4 as = ((const float4*)g_asrc)[s];
            float4 ex;
            ex.x = __expf(lrelu(as.x + ad.x) - mx.x);
            ex.y = __expf(lrelu(as.y + ad.y) - mx.y);
            ex.z = __expf(lrelu(as.z + ad.z) - mx.z);
            ex.w = __expf(lrelu(as.w + ad.w) - mx.w);
            den.x += ex.x; den.y += ex.y; den.z += ex.z; den.w += ex.w;
            s_ex4[g][t] = ex;
        }
        __syncthreads();
        int cnt = min(64, m - tile * 64);
        int lo = wig * 32;
        int myn = min(32, cnt - lo);
#pragma unroll 4
        for (int jj = 0; jj < myn; ++jj) {
            int idx = lo + jj;
            int s = s_srcv[g][idx];
            float4 e4 = s_ex4[g][idx];
            float2 hv = __half22float2(h2p[(unsigned)s * 32u + lane]);
            acc0.x += e4.x * hv.x; acc0.y += e4.x * hv.y;
            acc1.x += e4.y * hv.x; acc1.y += e4.y * hv.y;
            acc2.x += e4.z * hv.x; acc2.y += e4.z * hv.y;
            acc3.x += e4.w * hv.x; acc3.y += e4.w * hv.y;
        }
    }
    den = wsum4(den);
    if (lane == 0) s_red[g][wig] = den;
    if (wig == 1) {
        s_part[g][0][lane] = acc0; s_part[g][1][lane] = acc1;
        s_part[g][2][lane] = acc2; s_part[g][3][lane] = acc3;
    }
    __syncthreads();
    if (wig == 0 && valid) {
        float4 d0 = s_red[g][0], d1 = s_red[g][1];
        float4 dt = make_float4(d0.x + d1.x, d0.y + d1.y, d0.z + d1.z, d0.w + d1.w);
        float i0 = 1.f / (dt.x + 1e-16f), i1 = 1.f / (dt.y + 1e-16f);
        float i2 = 1.f / (dt.z + 1e-16f), i3 = 1.f / (dt.w + 1e-16f);
        float2 p0 = s_part[g][0][lane], p1 = s_part[g][1][lane];
        float2 p2 = s_part[g][2][lane], p3 = s_part[g][3][lane];
        __half2* o2 = (__half2*)g_hagg;
        unsigned rb = (unsigned)node * 128u;
        o2[rb + 0 * 32 + lane] = __floats2half2_rn((acc0.x + p0.x) * i0, (acc0.y + p0.y) * i0);
        o2[rb + 1 * 32 + lane] = __floats2half2_rn((acc1.x + p1.x) * i1, (acc1.y + p1.y) * i1);
        o2[rb + 2 * 32 + lane] = __floats2half2_rn((acc2.x + p2.x) * i2, (acc2.y + p2.y) * i2);
        o2[rb + 3 * 32 + lane] = __floats2half2_rn((acc3.x + p3.x) * i3, (acc3.y + p3.y) * i3);
    }
}

// ---------------- classifier: wmma GEMM (fp16 x fp16 -> fp32) + logits + log_softmax ----------------
__global__ void __launch_bounds__(256) k_classifier(
    const float* __restrict__ wc2, const float* __restrict__ bc2,
    float* __restrict__ out, int n) {
    extern __shared__ char smc[];
    __half* sA = (__half*)smc;               // [64][256] = 32KB
    __half* sW = (__half*)(smc + 32768);     // [256][64] = 32KB
    float*  sZ = (float*)(smc + 65536);      // [64][68] = 17408B
    __shared__ float sWc2[192];
    __shared__ float sB[64];
    __shared__ float sB2[3];
    __shared__ float sLg[192];
    __shared__ float sLse[64];

    int tid = threadIdx.x;
    int base = blockIdx.x * 64;

    {
        const uint4* wsrc = (const uint4*)g_Wcomb16;
        uint4* wdst = (uint4*)sW;
        for (int i = tid; i < 2048; i += 256) wdst[i] = wsrc[i];
    }
    if (tid < 192) sWc2[tid] = wc2[tid];
    if (tid < 64) sB[tid] = g_const[tid];
    if (tid < 3) sB2[tid] = bc2[tid];

    {
        const uint4* asrc = (const uint4*)g_hagg;
        uint4* adst = (uint4*)sA;
        uint4 z4 = make_uint4(0, 0, 0, 0);
        for (int i = tid; i < 2048; i += 256) {
            int r = i >> 5, c = i & 31;           // 32 uint4 per 256-half row
            adst[i] = (base + r < n) ? asrc[(unsigned)(base + r) * 32u + c] : z4;
        }
    }
    __syncthreads();

    // 8 warps x 2 accum tiles: warp w -> row-tile w>>1, col-tiles (w&1)*2, +1
    int w = tid >> 5;
    int rt = w >> 1, c0 = (w & 1) * 2;
    wmma::fragment<wmma::accumulator, 16, 16, 16, float> fc0, fc1;
    wmma::fill_fragment(fc0, 0.f);
    wmma::fill_fragment(fc1, 0.f);
#pragma unroll
    for (int kk = 0; kk < 16; ++kk) {
        wmma::fragment<wmma::matrix_a, 16, 16, 16, __half, wmma::row_major> fa;
        wmma::load_matrix_sync(fa, sA + rt * 16 * 256 + kk * 16, 256);
        wmma::fragment<wmma::matrix_b, 16, 16, 16, __half, wmma::row_major> fb;
        wmma::load_matrix_sync(fb, sW + kk * 16 * 64 + c0 * 16, 64);
        wmma::mma_sync(fc0, fa, fb, fc0);
        wmma::load_matrix_sync(fb, sW + kk * 16 * 64 + (c0 + 1) * 16, 64);
        wmma::mma_sync(fc1, fa, fb, fc1);
    }
    wmma::store_matrix_sync(sZ + rt * 16 * 68 + c0 * 16, fc0, 68, wmma::mem_row_major);
    wmma::store_matrix_sync(sZ + rt * 16 * 68 + (c0 + 1) * 16, fc1, 68, wmma::mem_row_major);
    __syncthreads();

    if (tid < 192) {
        int r = tid / 3, o = tid - 3 * r;
        float a = sB2[o];
#pragma unroll 8
        for (int c = 0; c < 64; ++c)
            a += fmaxf(sZ[r * 68 + c] + sB[c], 0.f) * sWc2[c * 3 + o];
        sLg[tid] = a;
    }
    __syncthreads();
    if (tid < 64) {
        float l0 = sLg[tid * 3 + 0], l1 = sLg[tid * 3 + 1], l2 = sLg[tid * 3 + 2];
        float mm = fmaxf(l0, fmaxf(l1, l2));
        sLse[tid] = mm + logf(__expf(l0 - mm) + __expf(l1 - mm) + __expf(l2 - mm));
    }
    __syncthreads();
    int nvalid = n - base; if (nvalid > 64) nvalid = 64;
    if (tid < nvalid * 3) out[base * 3 + tid] = sLg[tid] - sLse[tid / 3];
}

// ---------------- launch ----------------
extern "C" void kernel_launch(void* const* d_in, const int* in_sizes, int n_in,
                              void* d_out, int out_size) {
    const float* x     = (const float*)d_in[0];
    const void*  ei    = (const void*)d_in[1];
    const float* w1    = (const float*)d_in[2];
    const float* b1    = (const float*)d_in[3];
    const float* w2    = (const float*)d_in[4];
    const float* b2    = (const float*)d_in[5];
    const float* w3    = (const float*)d_in[6];
    const float* b3    = (const float*)d_in[7];
    const float* wg    = (const float*)d_in[8];
    const float* bg    = (const float*)d_in[9];
    const float* att_s = (const float*)d_in[10];
    const float* att_d = (const float*)d_in[11];
    const float* wc1   = (const float*)d_in[12];
    const float* bc1   = (const float*)d_in[13];
    const float* wc2   = (const float*)d_in[14];
    const float* bc2   = (const float*)d_in[15];
    float* out = (float*)d_out;

    int n = in_sizes[0] / 8;
    int e = in_sizes[1] / 2;

    // launches 1-5: gemm8 + CSR build (compressed) so launch #6 = k_gcn_agg
    k_gemm8<<<(n + 3) / 4, 256>>>(x, w1, n);                 // 1
    k_zero<<<(n + 255) / 256, 256>>>(n);                     // 2
    k_count<<<(e + 255) / 256, 256>>>(ei, e);                // 3
    k_scanall<<<1, 1024>>>(n, e);                            // 4
    k_scatter<<<(e + 255) / 256, 256>>>(ei, e);              // 5

    // GCN layer 1 aggregation  (launch #6 — ncu -s 5 -c 1 profiles THIS)
    k_gcn_agg<<<(n + 7) / 8, 256>>>(b1, n, 0);               // 6

    int gs = 444;
    // GCN layer 2 (residual)
    k_gemm64<<<gs, 256>>>(w2, n);
    k_gcn_agg<<<(n + 7) / 8, 256>>>(b2, n, 1);
    // GCN layer 3 (residual)
    k_gemm64<<<gs, 256>>>(w3, n);
    k_gcn_agg<<<(n + 7) / 8, 256>>>(b3, n, 1);
    // GAT (folded)
    k_att_pre<<<1, 512>>>(wg, att_s, att_d);
    k_wcomb<<<256, 64>>>(wg, wc1);
    k_const<<<1, 64>>>(wc1, bc1, bg);
    k_att<<<(n + 7) / 8, 256>>>(n);
    k_gat_agg2<<<(n + 3) / 4, 256>>>(n);
    // classifier (wmma) — 82944 B dynamic smem
    static int smem_set = 0;
    if (!smem_set) {
        cudaFuncSetAttribute(k_classifier, cudaFuncAttributeMaxDynamicSharedMemorySize, 98304);
        smem_set = 1;
    }
    k_classifier<<<(n + 63) / 64, 256, 82944>>>(wc2, bc2, out, n);
}

// round 13
// speedup vs baseline: 1.0838x; 1.0838x over previous
#include <cuda_runtime.h>
#include <cuda_fp16.h>
#include <mma.h>
#include <math.h>

using namespace nvcuda;

#define NN 100000
#define EE 1600000

// ---------------- device scratch (no allocations allowed) ----------------
__device__ int   g_count[NN];
__device__ int   g_rowptr[NN + 1];
__device__ int   g_cursor[NN];
__device__ int   g_blocksums[256];
__device__ float g_dinv[NN];
__device__ int2  g_epack[EE];              // (src, norm bits)
__device__ __half g_hlin[NN * 64];         // fp16 GCN linear output
__device__ float g_h[NN * 64];             // fp32 residual stream
__device__ __half g_h16[NN * 64];          // fp16 copy of final h for GAT gathers
__device__ __half g_hagg[NN * 256];        // fp16 per-head aggregated h
__device__ float g_asrc[NN * 4];
__device__ float g_adst[NN * 4];
__device__ float g_Wa[64 * 8];             // composite att weights
__device__ __half g_Wcomb16[256 * 64];     // folded wg.wc1 (fp16)
__device__ float g_const[64];              // folded bc1 + bg.wc1

// Inline dtype check: int64 ids < 2^31 => odd int32 words all zero.
__device__ __forceinline__ int detect64(const int* p) {
    int is64 = 1;
#pragma unroll
    for (int i = 1; i < 32; i += 2)
        if (p[i] != 0) is64 = 0;
    return is64;
}

__device__ __forceinline__ int ld_edge(const void* ei, int is64, long long idx) {
    if (is64) return (int)((const long long*)ei)[idx];
    return ((const int*)ei)[idx];
}

// ---------------- CSR build ----------------
__global__ void k_zero(int n) {
    int i = blockIdx.x * blockDim.x + threadIdx.x;
    if (i < n) g_count[i] = 0;
}

__global__ void k_count(const void* __restrict__ ei, int e) {
    int i = blockIdx.x * blockDim.x + threadIdx.x;
    if (i < e) {
        int is64 = detect64((const int*)ei);
        int d = ld_edge(ei, is64, (long long)e + i);
        atomicAdd(&g_count[d], 1);
    }
}

// multi-block 3-phase scan (measured ~6us total in rounds 3-11)
__global__ void k_scan1(int n) {
    __shared__ int s[512];
    int tid = threadIdx.x;
    int i = blockIdx.x * 512 + tid;
    int v = (i < n) ? g_count[i] : 0;
    s[tid] = v;
    __syncthreads();
    for (int off = 1; off < 512; off <<= 1) {
        int t = (tid >= off) ? s[tid - off] : 0;
        __syncthreads();
        s[tid] += t;
        __syncthreads();
    }
    if (i < n) g_rowptr[i] = s[tid] - v;   // exclusive
    if (tid == 511) g_blocksums[blockIdx.x] = s[511];
}

__global__ void k_scan2(int nb) {
    int run = 0;
    for (int b = 0; b < nb; ++b) { int t = g_blocksums[b]; g_blocksums[b] = run; run += t; }
}

__global__ void k_scan3(int n, int e) {
    int i = blockIdx.x * blockDim.x + threadIdx.x;
    if (i < n) {
        int rp = g_rowptr[i] + g_blocksums[i >> 9];
        g_rowptr[i] = rp;
        g_cursor[i] = rp;
        g_dinv[i] = rsqrtf((float)(g_count[i] + 1));
        if (i == 0) g_rowptr[n] = e;
    }
}

__global__ void k_scatter(const void* __restrict__ ei, int e) {
    int i = blockIdx.x * blockDim.x + threadIdx.x;
    if (i < e) {
        int is64 = detect64((const int*)ei);
        int s = ld_edge(ei, is64, i);
        int d = ld_edge(ei, is64, (long long)e + i);
        int p = atomicAdd(&g_cursor[d], 1);
        g_epack[p] = make_int2(s, __float_as_int(g_dinv[s] * g_dinv[d]));
    }
}

// ---------------- layer-1 GEMM: hlin = X[N,8] @ W[8,64] (fp16 out) ----------------
__global__ void k_gemm8(const float* __restrict__ X, const float* __restrict__ W, int n) {
    __shared__ float sx[4][8];
    int tid = threadIdx.x;
    int l = tid >> 6, col = tid & 63;
    int base = blockIdx.x * 4;
    if (tid < 32) {
        int r = base + (tid >> 3);
        sx[tid >> 3][tid & 7] = (r < n) ? X[r * 8 + (tid & 7)] : 0.f;
    }
    __syncthreads();
    int node = base + l;
    if (node < n) {
        float acc = 0.f;
#pragma unroll
        for (int k = 0; k < 8; ++k) acc += sx[l][k] * W[k * 64 + col];
        g_hlin[node * 64 + col] = __float2half(acc);
    }
}

// ---------------- GCN GEMM: hlin = g_h @ W[64,64], scalar W col in regs ----------------
__global__ void __launch_bounds__(256) k_gemm64(const float* __restrict__ W, int n) {
    float w[64];
    int tid = threadIdx.x;
    int l = tid >> 6, col = tid & 63;
#pragma unroll
    for (int k = 0; k < 64; ++k) w[k] = W[k * 64 + col];
    __shared__ float sx[4][64];
    for (int base = blockIdx.x * 4; base < n; base += gridDim.x * 4) {
        __syncthreads();
        int r = base + (tid >> 6);
        sx[tid >> 6][tid & 63] = (r < n) ? g_h[r * 64 + (tid & 63)] : 0.f;
        __syncthreads();
        int node = base + l;
        if (node < n) {
            float acc = 0.f;
#pragma unroll
            for (int k = 0; k < 64; ++k) acc += sx[l][k] * w[k];
            g_hlin[node * 64 + col] = __float2half(acc);
        }
    }
}

// ---------------- GCN aggregation: warp/node, fp16 gathers, 8-deep prefetch ----------------
__global__ void k_gcn_agg(const float* __restrict__ b, int n, int residual) {
    int tid = threadIdx.x, warp = tid >> 5, lane = tid & 31;
    int node = blockIdx.x * 8 + warp;
    if (node >= n) return;
    float di = g_dinv[node];
    float2 self = __half22float2(*(const __half2*)&g_hlin[node * 64 + 2 * lane]);
    float accx = di * di * self.x, accy = di * di * self.y;
    int beg = g_rowptr[node], end = g_rowptr[node + 1];
    int j = beg;
    for (; j + 7 < end; j += 8) {
        int2 ep[8];
#pragma unroll
        for (int q = 0; q < 8; ++q) ep[q] = g_epack[j + q];
#pragma unroll
        for (int q = 0; q < 8; ++q) {
            float w = __int_as_float(ep[q].y);
            float2 v = __half22float2(*(const __half2*)&g_hlin[ep[q].x * 64 + 2 * lane]);
            accx += w * v.x; accy += w * v.y;
        }
    }
    for (; j < end; ++j) {
        int2 ep = g_epack[j];
        float w = __int_as_float(ep.y);
        float2 v = __half22float2(*(const __half2*)&g_hlin[ep.x * 64 + 2 * lane]);
        accx += w * v.x; accy += w * v.y;
    }
    float2 bb = ((const float2*)b)[lane];
    float vx = fmaxf(accx + bb.x, 0.f), vy = fmaxf(accy + bb.y, 0.f);
    float2* H = (float2*)g_h;
    if (residual) {
        float2 p = H[node * 32 + lane];
        H[node * 32 + lane] = make_float2(p.x + vx, p.y + vy);
    } else {
        H[node * 32 + lane] = make_float2(vx, vy);
    }
}

// ---------------- composite attention weights: Wa = wg . att  (64x8) ----------------
__global__ void k_att_pre(const float* __restrict__ wg,
                          const float* __restrict__ att_s,
                          const float* __restrict__ att_d) {
    int t = threadIdx.x;
    int o = t & 7, k = t >> 3;
    int h = o & 3;
    const float* att = (o < 4) ? att_s : att_d;
    float s = 0.f;
#pragma unroll 8
    for (int c = 0; c < 64; ++c) s += wg[k * 256 + h * 64 + c] * att[h * 64 + c];
    g_Wa[k * 8 + o] = s;
}

// ---------------- folded classifier weights (fp16): Wcomb16 ----------------
__global__ void k_wcomb(const float* __restrict__ wg, const float* __restrict__ wc1) {
    int c = threadIdx.x;          // 64
    int hk = blockIdx.x;          // 256
    int h = hk >> 6, k = hk & 63;
    float s = 0.f;
#pragma unroll 8
    for (int j = 0; j < 64; ++j)
        s += wg[k * 256 + h * 64 + j] * wc1[(h * 64 + j) * 64 + c];
    g_Wcomb16[hk * 64 + c] = __float2half(s);
}

__global__ void k_const(const float* __restrict__ wc1, const float* __restrict__ bc1,
                        const float* __restrict__ bg) {
    int c = threadIdx.x;
    float s = bc1[c];
#pragma unroll 8
    for (int q = 0; q < 256; ++q) s += bg[q] * wc1[q * 64 + c];
    g_const[c] = s;
}

// ---------------- attention coeffs + fp16 h copy (warp per node) ----------------
__global__ void k_att(int n) {
    int tid = threadIdx.x, warp = tid >> 5, lane = tid & 31;
    int node = blockIdx.x * 8 + warp;
    if (node >= n) return;
    float2 hv = *(const float2*)&g_h[node * 64 + 2 * lane];
    ((__half2*)g_h16)[node * 32 + lane] = __floats2half2_rn(hv.x, hv.y);
    float r[8];
#pragma unroll
    for (int o = 0; o < 8; ++o) {
        r[o] = hv.x * g_Wa[(2 * lane) * 8 + o] + hv.y * g_Wa[(2 * lane + 1) * 8 + o];
#pragma unroll
        for (int off = 16; off > 0; off >>= 1)
            r[o] += __shfl_xor_sync(0xffffffffu, r[o], off);
    }
    if (lane < 4)      g_asrc[node * 4 + lane] = r[lane];
    else if (lane < 8) g_adst[node * 4 + lane - 4] = r[lane];
}

// ---------------- GAT softmax + 64-dim aggregation (linearity fold) ----------------
__device__ __forceinline__ float lrelu(float e) { return e > 0.f ? e : 0.2f * e; }

__device__ __forceinline__ float4 wmax4(float4 v) {
#pragma unroll
    for (int o = 16; o > 0; o >>= 1) {
        v.x = fmaxf(v.x, __shfl_xor_sync(0xffffffffu, v.x, o));
        v.y = fmaxf(v.y, __shfl_xor_sync(0xffffffffu, v.y, o));
        v.z = fmaxf(v.z, __shfl_xor_sync(0xffffffffu, v.z, o));
        v.w = fmaxf(v.w, __shfl_xor_sync(0xffffffffu, v.w, o));
    }
    return v;
}

__device__ __forceinline__ float4 wsum4(float4 v) {
#pragma unroll
    for (int o = 16; o > 0; o >>= 1) {
        v.x += __shfl_xor_sync(0xffffffffu, v.x, o);
        v.y += __shfl_xor_sync(0xffffffffu, v.y, o);
        v.z += __shfl_xor_sync(0xffffffffu, v.z, o);
        v.w += __shfl_xor_sync(0xffffffffu, v.w, o);
    }
    return v;
}

__global__ void __launch_bounds__(256) k_gat_agg2(int n) {
    int tid = threadIdx.x;
    int g = tid >> 6, t = tid & 63;
    int wig = (t >> 5) & 1;
    int lane = tid & 31;
    int node = blockIdx.x * 4 + g;
    bool valid = node < n;

    __shared__ float4 s_ex4[4][64];
    __shared__ int    s_srcv[4][64];
    __shared__ float4 s_red[4][2];
    __shared__ float2 s_part[4][4][32];
    __shared__ int    s_nt[4];

    int beg = 0, m = 0;
    if (valid) { beg = g_rowptr[node]; m = g_rowptr[node + 1] - beg + 1; }

    float4 ad = valid ? ((const float4*)g_adst)[node] : make_float4(0, 0, 0, 0);

    float4 mx = make_float4(-1e30f, -1e30f, -1e30f, -1e30f);
    for (int j = t; j < m; j += 64) {
        int s = (j < m - 1) ? g_epack[beg + j].x : node;
        float4 as = ((const float4*)g_asrc)[s];
        mx.x = fmaxf(mx.x, lrelu(as.x + ad.x));
        mx.y = fmaxf(mx.y, lrelu(as.y + ad.y));
        mx.z = fmaxf(mx.z, lrelu(as.z + ad.z));
        mx.w = fmaxf(mx.w, lrelu(as.w + ad.w));
    }
    mx = wmax4(mx);
    if (lane == 0) s_red[g][wig] = mx;
    if (t == 0) s_nt[g] = (m + 63) >> 6;
    __syncthreads();
    {
        float4 a = s_red[g][0], b2 = s_red[g][1];
        mx.x = fmaxf(a.x, b2.x); mx.y = fmaxf(a.y, b2.y);
        mx.z = fmaxf(a.z, b2.z); mx.w = fmaxf(a.w, b2.w);
    }
    int ntmax = max(max(s_nt[0], s_nt[1]), max(s_nt[2], s_nt[3]));

    float2 acc0 = make_float2(0, 0), acc1 = make_float2(0, 0);
    float2 acc2 = make_float2(0, 0), acc3 = make_float2(0, 0);
    float4 den = make_float4(0, 0, 0, 0);
    const __half2* h2p = (const __half2*)g_h16;

    for (int tile = 0; tile < ntmax; ++tile) {
        __syncthreads();
        int j = tile * 64 + t;
        if (j < m) {
            int s = (j < m - 1) ? g_epack[beg + j].x : node;
            s_srcv[g][t] = s;
            float4 as = ((const float4*)g_asrc)[s];
            float4 ex;
            ex.x = __expf(lrelu(as.x + ad.x) - mx.x);
            ex.y = __expf(lrelu(as.y + ad.y) - mx.y);
            ex.z = __expf(lrelu(as.z + ad.z) - mx.z);
            ex.w = __expf(lrelu(as.w + ad.w) - mx.w);
            den.x += ex.x; den.y += ex.y; den.z += ex.z; den.w += ex.w;
            s_ex4[g][t] = ex;
        }
        __syncthreads();
        int cnt = min(64, m - tile * 64);
        int lo = wig * 32;
        int myn = min(32, cnt - lo);
#pragma unroll 4
        for (int jj = 0; jj < myn; ++jj) {
            int idx = lo + jj;
            int s = s_srcv[g][idx];
            float4 e4 = s_ex4[g][idx];
            float2 hv = __half22float2(h2p[(unsigned)s * 32u + lane]);
            acc0.x += e4.x * hv.x; acc0.y += e4.x * hv.y;
            acc1.x += e4.y * hv.x; acc1.y += e4.y * hv.y;
            acc2.x += e4.z * hv.x; acc2.y += e4.z * hv.y;
            acc3.x += e4.w * hv.x; acc3.y += e4.w * hv.y;
        }
    }
    den = wsum4(den);
    if (lane == 0) s_red[g][wig] = den;
    if (wig == 1) {
        s_part[g][0][lane] = acc0; s_part[g][1][lane] = acc1;
        s_part[g][2][lane] = acc2; s_part[g][3][lane] = acc3;
    }
    __syncthreads();
    if (wig == 0 && valid) {
        float4 d0 = s_red[g][0], d1 = s_red[g][1];
        float4 dt = make_float4(d0.x + d1.x, d0.y + d1.y, d0.z + d1.z, d0.w + d1.w);
        float i0 = 1.f / (dt.x + 1e-16f), i1 = 1.f / (dt.y + 1e-16f);
        float i2 = 1.f / (dt.z + 1e-16f), i3 = 1.f / (dt.w + 1e-16f);
        float2 p0 = s_part[g][0][lane], p1 = s_part[g][1][lane];
        float2 p2 = s_part[g][2][lane], p3 = s_part[g][3][lane];
        __half2* o2 = (__half2*)g_hagg;
        unsigned rb = (unsigned)node * 128u;
        o2[rb + 0 * 32 + lane] = __floats2half2_rn((acc0.x + p0.x) * i0, (acc0.y + p0.y) * i0);
        o2[rb + 1 * 32 + lane] = __floats2half2_rn((acc1.x + p1.x) * i1, (acc1.y + p1.y) * i1);
        o2[rb + 2 * 32 + lane] = __floats2half2_rn((acc2.x + p2.x) * i2, (acc2.y + p2.y) * i2);
        o2[rb + 3 * 32 + lane] = __floats2half2_rn((acc3.x + p3.x) * i3, (acc3.y + p3.y) * i3);
    }
}

// ---------------- classifier: wmma GEMM (fp16 x fp16 -> fp32) + logits + log_softmax ----------------
__global__ void __launch_bounds__(256) k_classifier(
    const float* __restrict__ wc2, const float* __restrict__ bc2,
    float* __restrict__ out, int n) {
    extern __shared__ char smc[];
    __half* sA = (__half*)smc;               // [64][256] = 32KB
    __half* sW = (__half*)(smc + 32768);     // [256][64] = 32KB
    float*  sZ = (float*)(smc + 65536);      // [64][68] = 17408B
    __shared__ float sWc2[192];
    __shared__ float sB[64];
    __shared__ float sB2[3];
    __shared__ float sLg[192];
    __shared__ float sLse[64];

    int tid = threadIdx.x;
    int base = blockIdx.x * 64;

    {
        const uint4* wsrc = (const uint4*)g_Wcomb16;
        uint4* wdst = (uint4*)sW;
        for (int i = tid; i < 2048; i += 256) wdst[i] = wsrc[i];
    }
    if (tid < 192) sWc2[tid] = wc2[tid];
    if (tid < 64) sB[tid] = g_const[tid];
    if (tid < 3) sB2[tid] = bc2[tid];

    {
        const uint4* asrc = (const uint4*)g_hagg;
        uint4* adst = (uint4*)sA;
        uint4 z4 = make_uint4(0, 0, 0, 0);
        for (int i = tid; i < 2048; i += 256) {
            int r = i >> 5, c = i & 31;
            adst[i] = (base + r < n) ? asrc[(unsigned)(base + r) * 32u + c] : z4;
        }
    }
    __syncthreads();

    int w = tid >> 5;
    int rt = w >> 1, c0 = (w & 1) * 2;
    wmma::fragment<wmma::accumulator, 16, 16, 16, float> fc0, fc1;
    wmma::fill_fragment(fc0, 0.f);
    wmma::fill_fragment(fc1, 0.f);
#pragma unroll
    for (int kk = 0; kk < 16; ++kk) {
        wmma::fragment<wmma::matrix_a, 16, 16, 16, __half, wmma::row_major> fa;
        wmma::load_matrix_sync(fa, sA + rt * 16 * 256 + kk * 16, 256);
        wmma::fragment<wmma::matrix_b, 16, 16, 16, __half, wmma::row_major> fb;
        wmma::load_matrix_sync(fb, sW + kk * 16 * 64 + c0 * 16, 64);
        wmma::mma_sync(fc0, fa, fb, fc0);
        wmma::load_matrix_sync(fb, sW + kk * 16 * 64 + (c0 + 1) * 16, 64);
        wmma::mma_sync(fc1, fa, fb, fc1);
    }
    wmma::store_matrix_sync(sZ + rt * 16 * 68 + c0 * 16, fc0, 68, wmma::mem_row_major);
    wmma::store_matrix_sync(sZ + rt * 16 * 68 + (c0 + 1) * 16, fc1, 68, wmma::mem_row_major);
    __syncthreads();

    if (tid < 192) {
        int r = tid / 3, o = tid - 3 * r;
        float a = sB2[o];
#pragma unroll 8
        for (int c = 0; c < 64; ++c)
            a += fmaxf(sZ[r * 68 + c] + sB[c], 0.f) * sWc2[c * 3 + o];
        sLg[tid] = a;
    }
    __syncthreads();
    if (tid < 64) {
        float l0 = sLg[tid * 3 + 0], l1 = sLg[tid * 3 + 1], l2 = sLg[tid * 3 + 2];
        float mm = fmaxf(l0, fmaxf(l1, l2));
        sLse[tid] = mm + logf(__expf(l0 - mm) + __expf(l1 - mm) + __expf(l2 - mm));
    }
    __syncthreads();
    int nvalid = n - base; if (nvalid > 64) nvalid = 64;
    if (tid < nvalid * 3) out[base * 3 + tid] = sLg[tid] - sLse[tid / 3];
}

// ---------------- launch ----------------
extern "C" void kernel_launch(void* const* d_in, const int* in_sizes, int n_in,
                              void* d_out, int out_size) {
    const float* x     = (const float*)d_in[0];
    const void*  ei    = (const void*)d_in[1];
    const float* w1    = (const float*)d_in[2];
    const float* b1    = (const float*)d_in[3];
    const float* w2    = (const float*)d_in[4];
    const float* b2    = (const float*)d_in[5];
    const float* w3    = (const float*)d_in[6];
    const float* b3    = (const float*)d_in[7];
    const float* wg    = (const float*)d_in[8];
    const float* bg    = (const float*)d_in[9];
    const float* att_s = (const float*)d_in[10];
    const float* att_d = (const float*)d_in[11];
    const float* wc1   = (const float*)d_in[12];
    const float* bc1   = (const float*)d_in[13];
    const float* wc2   = (const float*)d_in[14];
    const float* bc2   = (const float*)d_in[15];
    float* out = (float*)d_out;

    int n = in_sizes[0] / 8;
    int e = in_sizes[1] / 2;
    int nb512 = (n + 511) / 512;

    // CSR build (multi-block scan) + layer-1 GEMM
    k_gemm8<<<(n + 3) / 4, 256>>>(x, w1, n);
    k_zero<<<(n + 255) / 256, 256>>>(n);
    k_count<<<(e + 255) / 256, 256>>>(ei, e);
    k_scan1<<<nb512, 512>>>(n);
    k_scan2<<<1, 1>>>(nb512);
    k_scan3<<<(n + 255) / 256, 256>>>(n, e);
    k_scatter<<<(e + 255) / 256, 256>>>(ei, e);

    // GCN layer 1
    k_gcn_agg<<<(n + 7) / 8, 256>>>(b1, n, 0);
    int gs = 444;
    // GCN layer 2 (residual)
    k_gemm64<<<gs, 256>>>(w2, n);
    k_gcn_agg<<<(n + 7) / 8, 256>>>(b2, n, 1);
    // GCN layer 3 (residual)
    k_gemm64<<<gs, 256>>>(w3, n);
    k_gcn_agg<<<(n + 7) / 8, 256>>>(b3, n, 1);
    // GAT (folded)
    k_att_pre<<<1, 512>>>(wg, att_s, att_d);
    k_wcomb<<<256, 64>>>(wg, wc1);
    k_const<<<1, 64>>>(wc1, bc1, bg);
    k_att<<<(n + 7) / 8, 256>>>(n);
    k_gat_agg2<<<(n + 3) / 4, 256>>>(n);
    // classifier (wmma) — 82944 B dynamic smem
    static int smem_set = 0;
    if (!smem_set) {
        cudaFuncSetAttribute(k_classifier, cudaFuncAttributeMaxDynamicSharedMemorySize, 98304);
        smem_set = 1;
    }
    k_classifier<<<(n + 63) / 64, 256, 82944>>>(wc2, bc2, out, n);
}

// round 14
// speedup vs baseline: 1.3039x; 1.2030x over previous
#include <cuda_runtime.h>
#include <cuda_fp16.h>
#include <mma.h>
#include <math.h>

using namespace nvcuda;

#define NN 100000
#define EE 1600000

// ---------------- device scratch (no allocations allowed) ----------------
__device__ int   g_count[NN];
__device__ int   g_rowptr[NN + 1];
__device__ int   g_cursor[NN];
__device__ int   g_blocksums[256];
__device__ float g_dinv[NN];
__device__ int2  g_epack[EE];              // (src, norm bits)
__device__ __half g_hlin[NN * 64];         // fp16 GCN linear output
__device__ float g_h[NN * 64];             // fp32 residual stream
__device__ __half g_h16[NN * 64];          // fp16 final h for GAT gathers
__device__ __half g_hagg[NN * 256];        // fp16 per-head aggregated h
__device__ float g_asrc[NN * 4];
__device__ float g_adst[NN * 4];
__device__ float g_Wa[64 * 8];             // composite att weights
__device__ __half g_Wcomb16[256 * 64];     // folded wg.wc1 (fp16)
__device__ float g_const[64];              // folded bc1 + bg.wc1

// Inline dtype check: int64 ids < 2^31 => odd int32 words all zero.
__device__ __forceinline__ int detect64(const int* p) {
    int is64 = 1;
#pragma unroll
    for (int i = 1; i < 32; i += 2)
        if (p[i] != 0) is64 = 0;
    return is64;
}

__device__ __forceinline__ int ld_edge(const void* ei, int is64, long long idx) {
    if (is64) return (int)((const long long*)ei)[idx];
    return ((const int*)ei)[idx];
}

// ---------------- CSR build ----------------
__global__ void k_zero(int n) {
    int i = blockIdx.x * blockDim.x + threadIdx.x;
    if (i < n) g_count[i] = 0;
}

__global__ void k_count(const void* __restrict__ ei, int e) {
    int i = blockIdx.x * blockDim.x + threadIdx.x;
    if (i < e) {
        int is64 = detect64((const int*)ei);
        int d = ld_edge(ei, is64, (long long)e + i);
        atomicAdd(&g_count[d], 1);
    }
}

__global__ void k_scan1(int n) {
    __shared__ int s[512];
    int tid = threadIdx.x;
    int i = blockIdx.x * 512 + tid;
    int v = (i < n) ? g_count[i] : 0;
    s[tid] = v;
    __syncthreads();
    for (int off = 1; off < 512; off <<= 1) {
        int t = (tid >= off) ? s[tid - off] : 0;
        __syncthreads();
        s[tid] += t;
        __syncthreads();
    }
    if (i < n) g_rowptr[i] = s[tid] - v;   // exclusive
    if (tid == 511) g_blocksums[blockIdx.x] = s[511];
}

// 256-thread block shfl-scan over block sums (nb <= 256)
__global__ void k_scan2(int nb) {
    __shared__ int ws[8];
    int tid = threadIdx.x, lane = tid & 31, w = tid >> 5;
    int v = (tid < nb) ? g_blocksums[tid] : 0;
    int x = v;
#pragma unroll
    for (int off = 1; off < 32; off <<= 1) {
        int y = __shfl_up_sync(0xffffffffu, x, off);
        if (lane >= off) x += y;
    }
    if (lane == 31) ws[w] = x;
    __syncthreads();
    if (w == 0) {
        int t = (lane < 8) ? ws[lane] : 0;
#pragma unroll
        for (int off = 1; off < 8; off <<= 1) {
            int y = __shfl_up_sync(0xffffffffu, t, off);
            if (lane >= off) t += y;
        }
        if (lane < 8) ws[lane] = t;
    }
    __syncthreads();
    int excl = x - v + (w ? ws[w - 1] : 0);
    if (tid < nb) g_blocksums[tid] = excl;
}

__global__ void k_scan3(int n, int e) {
    int i = blockIdx.x * blockDim.x + threadIdx.x;
    if (i < n) {
        int rp = g_rowptr[i] + g_blocksums[i >> 9];
        g_rowptr[i] = rp;
        g_cursor[i] = rp;
        g_dinv[i] = rsqrtf((float)(g_count[i] + 1));
        if (i == 0) g_rowptr[n] = e;
    }
}

__global__ void k_scatter(const void* __restrict__ ei, int e) {
    int i = blockIdx.x * blockDim.x + threadIdx.x;
    if (i < e) {
        int is64 = detect64((const int*)ei);
        int s = ld_edge(ei, is64, i);
        int d = ld_edge(ei, is64, (long long)e + i);
        int p = atomicAdd(&g_cursor[d], 1);
        g_epack[p] = make_int2(s, __float_as_int(g_dinv[s] * g_dinv[d]));
    }
}

// ---------------- layer-1 GEMM: hlin = X[N,8] @ W[8,64] (fp16 out) ----------------
__global__ void k_gemm8(const float* __restrict__ X, const float* __restrict__ W, int n) {
    __shared__ float sx[4][8];
    int tid = threadIdx.x;
    int l = tid >> 6, col = tid & 63;
    int base = blockIdx.x * 4;
    if (tid < 32) {
        int r = base + (tid >> 3);
        sx[tid >> 3][tid & 7] = (r < n) ? X[r * 8 + (tid & 7)] : 0.f;
    }
    __syncthreads();
    int node = base + l;
    if (node < n) {
        float acc = 0.f;
#pragma unroll
        for (int k = 0; k < 8; ++k) acc += sx[l][k] * W[k * 64 + col];
        g_hlin[node * 64 + col] = __float2half(acc);
    }
}

// ---------------- GCN GEMM: hlin = g_h @ W[64,64], scalar W col in regs ----------------
__global__ void __launch_bounds__(256) k_gemm64(const float* __restrict__ W, int n) {
    float w[64];
    int tid = threadIdx.x;
    int l = tid >> 6, col = tid & 63;
#pragma unroll
    for (int k = 0; k < 64; ++k) w[k] = W[k * 64 + col];
    __shared__ float sx[4][64];
    for (int base = blockIdx.x * 4; base < n; base += gridDim.x * 4) {
        __syncthreads();
        int r = base + (tid >> 6);
        sx[tid >> 6][tid & 63] = (r < n) ? g_h[r * 64 + (tid & 63)] : 0.f;
        __syncthreads();
        int node = base + l;
        if (node < n) {
            float acc = 0.f;
#pragma unroll
            for (int k = 0; k < 64; ++k) acc += sx[l][k] * w[k];
            g_hlin[node * 64 + col] = __float2half(acc);
        }
    }
}

// ---------------- GCN aggregation: warp/node, fp16 gathers; optional fused att ----------------
__global__ void k_gcn_agg(const float* __restrict__ b, int n, int residual, int do_att) {
    int tid = threadIdx.x, warp = tid >> 5, lane = tid & 31;
    int node = blockIdx.x * 8 + warp;
    if (node >= n) return;
    float di = g_dinv[node];
    float2 self = __half22float2(*(const __half2*)&g_hlin[node * 64 + 2 * lane]);
    float accx = di * di * self.x, accy = di * di * self.y;
    int beg = g_rowptr[node], end = g_rowptr[node + 1];
    int j = beg;
    for (; j + 7 < end; j += 8) {
        int2 ep[8];
#pragma unroll
        for (int q = 0; q < 8; ++q) ep[q] = g_epack[j + q];
#pragma unroll
        for (int q = 0; q < 8; ++q) {
            float w = __int_as_float(ep[q].y);
            float2 v = __half22float2(*(const __half2*)&g_hlin[ep[q].x * 64 + 2 * lane]);
            accx += w * v.x; accy += w * v.y;
        }
    }
    for (; j < end; ++j) {
        int2 ep = g_epack[j];
        float w = __int_as_float(ep.y);
        float2 v = __half22float2(*(const __half2*)&g_hlin[ep.x * 64 + 2 * lane]);
        accx += w * v.x; accy += w * v.y;
    }
    float2 bb = ((const float2*)b)[lane];
    float vx = fmaxf(accx + bb.x, 0.f), vy = fmaxf(accy + bb.y, 0.f);
    float2* H = (float2*)g_h;
    float fx, fy;
    if (residual) {
        float2 p = H[node * 32 + lane];
        fx = p.x + vx; fy = p.y + vy;
    } else {
        fx = vx; fy = vy;
    }
    H[node * 32 + lane] = make_float2(fx, fy);
    if (do_att) {
        // fp16 copy for GAT gathers
        ((__half2*)g_h16)[node * 32 + lane] = __floats2half2_rn(fx, fy);
        // attention coefficients via composite Wa
        float r[8];
#pragma unroll
        for (int o = 0; o < 8; ++o) {
            r[o] = fx * g_Wa[(2 * lane) * 8 + o] + fy * g_Wa[(2 * lane + 1) * 8 + o];
#pragma unroll
            for (int off = 16; off > 0; off >>= 1)
                r[o] += __shfl_xor_sync(0xffffffffu, r[o], off);
        }
        if (lane < 4)      g_asrc[node * 4 + lane] = r[lane];
        else if (lane < 8) g_adst[node * 4 + lane - 4] = r[lane];
    }
}

// ---------------- merged precompute: Wa, Wcomb16, const (grid 256 x 64) ----------------
__global__ void k_prep(const float* __restrict__ wg,
                       const float* __restrict__ att_s,
                       const float* __restrict__ att_d,
                       const float* __restrict__ wc1,
                       const float* __restrict__ bc1,
                       const float* __restrict__ bg) {
    int c = threadIdx.x;          // 64
    int hk = blockIdx.x;          // 256: h = hk>>6, k = hk&63
    int h = hk >> 6, k = hk & 63;
    float s = 0.f;
#pragma unroll 8
    for (int j = 0; j < 64; ++j)
        s += wg[k * 256 + h * 64 + j] * wc1[(h * 64 + j) * 64 + c];
    g_Wcomb16[hk * 64 + c] = __float2half(s);

    if (hk < 64 && c < 8) {       // Wa[k=hk][o=c]
        int hh = c & 3;
        const float* att = (c < 4) ? att_s : att_d;
        float t = 0.f;
#pragma unroll 8
        for (int q = 0; q < 64; ++q) t += wg[hk * 256 + hh * 64 + q] * att[hh * 64 + q];
        g_Wa[hk * 8 + c] = t;
    }
    if (hk == 64) {               // const[c]
        float t = bc1[c];
#pragma unroll 8
        for (int q = 0; q < 256; ++q) t += bg[q] * wc1[q * 64 + c];
        g_const[c] = t;
    }
}

// ---------------- GAT softmax + 64-dim aggregation: WARP PER NODE ----------------
__device__ __forceinline__ float lrelu(float e) { return e > 0.f ? e : 0.2f * e; }

__device__ __forceinline__ float4 wmax4(float4 v) {
#pragma unroll
    for (int o = 16; o > 0; o >>= 1) {
        v.x = fmaxf(v.x, __shfl_xor_sync(0xffffffffu, v.x, o));
        v.y = fmaxf(v.y, __shfl_xor_sync(0xffffffffu, v.y, o));
        v.z = fmaxf(v.z, __shfl_xor_sync(0xffffffffu, v.z, o));
        v.w = fmaxf(v.w, __shfl_xor_sync(0xffffffffu, v.w, o));
    }
    return v;
}

__device__ __forceinline__ float4 wsum4(float4 v) {
#pragma unroll
    for (int o = 16; o > 0; o >>= 1) {
        v.x += __shfl_xor_sync(0xffffffffu, v.x, o);
        v.y += __shfl_xor_sync(0xffffffffu, v.y, o);
        v.z += __shfl_xor_sync(0xffffffffu, v.z, o);
        v.w += __shfl_xor_sync(0xffffffffu, v.w, o);
    }
    return v;
}

__global__ void __launch_bounds__(256) k_gat_agg3(int n) {
    int tid = threadIdx.x, warp = tid >> 5, lane = tid & 31;
    int node = blockIdx.x * 8 + warp;
    __shared__ float4 s_ex[8][32];
    __shared__ int    s_src[8][32];
    if (node >= n) return;

    int beg = g_rowptr[node];
    int m = g_rowptr[node + 1] - beg + 1;   // + self loop at index m-1
    float4 ad = ((const float4*)g_adst)[node];
    const float4* as4 = (const float4*)g_asrc;
    bool small = (m <= 32);

    // pass 1: per-head max (register-cache e and s when m<=32)
    float4 mx = make_float4(-1e30f, -1e30f, -1e30f, -1e30f);
    float4 ec = make_float4(0, 0, 0, 0);
    int sc = node;
    for (int j = lane; j < m; j += 32) {
        int s = (j < m - 1) ? g_epack[beg + j].x : node;
        float4 as = as4[s];
        float4 e;
        e.x = lrelu(as.x + ad.x); e.y = lrelu(as.y + ad.y);
        e.z = lrelu(as.z + ad.z); e.w = lrelu(as.w + ad.w);
        mx.x = fmaxf(mx.x, e.x); mx.y = fmaxf(mx.y, e.y);
        mx.z = fmaxf(mx.z, e.z); mx.w = fmaxf(mx.w, e.w);
        if (small) { ec = e; sc = s; }
    }
    mx = wmax4(mx);

    // chunked: exp + stage + gather
    float4 den = make_float4(0, 0, 0, 0);
    float2 a0 = make_float2(0, 0), a1 = make_float2(0, 0);
    float2 a2 = make_float2(0, 0), a3 = make_float2(0, 0);
    const __half2* h2p = (const __half2*)g_h16;

    for (int c0 = 0; c0 < m; c0 += 32) {
        int j = c0 + lane;
        float4 ex = make_float4(0, 0, 0, 0);
        int s = node;
        if (j < m) {
            float4 e;
            if (small) { e = ec; s = sc; }
            else {
                s = (j < m - 1) ? g_epack[beg + j].x : node;
                float4 as = as4[s];
                e.x = lrelu(as.x + ad.x); e.y = lrelu(as.y + ad.y);
                e.z = lrelu(as.z + ad.z); e.w = lrelu(as.w + ad.w);
            }
            ex.x = __expf(e.x - mx.x); ex.y = __expf(e.y - mx.y);
            ex.z = __expf(e.z - mx.z); ex.w = __expf(e.w - mx.w);
            den.x += ex.x; den.y += ex.y; den.z += ex.z; den.w += ex.w;
        }
        __syncwarp();
        s_src[warp][lane] = s;
        s_ex[warp][lane] = ex;
        __syncwarp();
        int cnt = min(32, m - c0);
#pragma unroll 4
        for (int jj = 0; jj < cnt; ++jj) {
            float4 e4 = s_ex[warp][jj];
            int s2 = s_src[warp][jj];
            float2 hv = __half22float2(h2p[(unsigned)s2 * 32u + lane]);
            a0.x += e4.x * hv.x; a0.y += e4.x * hv.y;
            a1.x += e4.y * hv.x; a1.y += e4.y * hv.y;
            a2.x += e4.z * hv.x; a2.y += e4.z * hv.y;
            a3.x += e4.w * hv.x; a3.y += e4.w * hv.y;
        }
        __syncwarp();
    }
    den = wsum4(den);
    float i0 = 1.f / (den.x + 1e-16f), i1 = 1.f / (den.y + 1e-16f);
    float i2 = 1.f / (den.z + 1e-16f), i3 = 1.f / (den.w + 1e-16f);
    __half2* o2 = (__half2*)g_hagg;
    unsigned rb = (unsigned)node * 128u;
    o2[rb + 0 * 32 + lane] = __floats2half2_rn(a0.x * i0, a0.y * i0);
    o2[rb + 1 * 32 + lane] = __floats2half2_rn(a1.x * i1, a1.y * i1);
    o2[rb + 2 * 32 + lane] = __floats2half2_rn(a2.x * i2, a2.y * i2);
    o2[rb + 3 * 32 + lane] = __floats2half2_rn(a3.x * i3, a3.y * i3);
}

// ---------------- classifier: wmma GEMM (fp16 x fp16 -> fp32) + logits + log_softmax ----------------
__global__ void __launch_bounds__(256) k_classifier(
    const float* __restrict__ wc2, const float* __restrict__ bc2,
    float* __restrict__ out, int n) {
    extern __shared__ char smc[];
    __half* sA = (__half*)smc;               // [64][256] = 32KB
    __half* sW = (__half*)(smc + 32768);     // [256][64] = 32KB
    float*  sZ = (float*)(smc + 65536);      // [64][68]
    __shared__ float sWc2[192];
    __shared__ float sB[64];
    __shared__ float sB2[3];
    __shared__ float sLg[192];
    __shared__ float sLse[64];

    int tid = threadIdx.x;
    int base = blockIdx.x * 64;

    {
        const uint4* wsrc = (const uint4*)g_Wcomb16;
        uint4* wdst = (uint4*)sW;
        for (int i = tid; i < 2048; i += 256) wdst[i] = wsrc[i];
    }
    if (tid < 192) sWc2[tid] = wc2[tid];
    if (tid < 64) sB[tid] = g_const[tid];
    if (tid < 3) sB2[tid] = bc2[tid];

    {
        const uint4* asrc = (const uint4*)g_hagg;
        uint4* adst = (uint4*)sA;
        uint4 z4 = make_uint4(0, 0, 0, 0);
        for (int i = tid; i < 2048; i += 256) {
            int r = i >> 5, c = i & 31;
            adst[i] = (base + r < n) ? asrc[(unsigned)(base + r) * 32u + c] : z4;
        }
    }
    __syncthreads();

    int w = tid >> 5;
    int rt = w >> 1, c0 = (w & 1) * 2;
    wmma::fragment<wmma::accumulator, 16, 16, 16, float> fc0, fc1;
    wmma::fill_fragment(fc0, 0.f);
    wmma::fill_fragment(fc1, 0.f);
#pragma unroll
    for (int kk = 0; kk < 16; ++kk) {
        wmma::fragment<wmma::matrix_a, 16, 16, 16, __half, wmma::row_major> fa;
        wmma::load_matrix_sync(fa, sA + rt * 16 * 256 + kk * 16, 256);
        wmma::fragment<wmma::matrix_b, 16, 16, 16, __half, wmma::row_major> fb;
        wmma::load_matrix_sync(fb, sW + kk * 16 * 64 + c0 * 16, 64);
        wmma::mma_sync(fc0, fa, fb, fc0);
        wmma::load_matrix_sync(fb, sW + kk * 16 * 64 + (c0 + 1) * 16, 64);
        wmma::mma_sync(fc1, fa, fb, fc1);
    }
    wmma::store_matrix_sync(sZ + rt * 16 * 68 + c0 * 16, fc0, 68, wmma::mem_row_major);
    wmma::store_matrix_sync(sZ + rt * 16 * 68 + (c0 + 1) * 16, fc1, 68, wmma::mem_row_major);
    __syncthreads();

    if (tid < 192) {
        int r = tid / 3, o = tid - 3 * r;
        float a = sB2[o];
#pragma unroll 8
        for (int c = 0; c < 64; ++c)
            a += fmaxf(sZ[r * 68 + c] + sB[c], 0.f) * sWc2[c * 3 + o];
        sLg[tid] = a;
    }
    __syncthreads();
    if (tid < 64) {
        float l0 = sLg[tid * 3 + 0], l1 = sLg[tid * 3 + 1], l2 = sLg[tid * 3 + 2];
        float mm = fmaxf(l0, fmaxf(l1, l2));
        sLse[tid] = mm + logf(__expf(l0 - mm) + __expf(l1 - mm) + __expf(l2 - mm));
    }
    __syncthreads();
    int nvalid = n - base; if (nvalid > 64) nvalid = 64;
    if (tid < nvalid * 3) out[base * 3 + tid] = sLg[tid] - sLse[tid / 3];
}

// ---------------- launch ----------------
extern "C" void kernel_launch(void* const* d_in, const int* in_sizes, int n_in,
                              void* d_out, int out_size) {
    const float* x     = (const float*)d_in[0];
    const void*  ei    = (const void*)d_in[1];
    const float* w1    = (const float*)d_in[2];
    const float* b1    = (const float*)d_in[3];
    const float* w2    = (const float*)d_in[4];
    const float* b2    = (const float*)d_in[5];
    const float* w3    = (const float*)d_in[6];
    const float* b3    = (const float*)d_in[7];
    const float* wg    = (const float*)d_in[8];
    const float* bg    = (const float*)d_in[9];
    const float* att_s = (const float*)d_in[10];
    const float* att_d = (const float*)d_in[11];
    const float* wc1   = (const float*)d_in[12];
    const float* bc1   = (const float*)d_in[13];
    const float* wc2   = (const float*)d_in[14];
    const float* bc2   = (const float*)d_in[15];
    float* out = (float*)d_out;

    int n = in_sizes[0] / 8;
    int e = in_sizes[1] / 2;
    int nb512 = (n + 511) / 512;

    // CSR build + layer-1 GEMM + precomputes
    k_gemm8<<<(n + 3) / 4, 256>>>(x, w1, n);
    k_zero<<<(n + 255) / 256, 256>>>(n);
    k_count<<<(e + 255) / 256, 256>>>(ei, e);
    k_scan1<<<nb512, 512>>>(n);
    k_scan2<<<1, 256>>>(nb512);
    k_scan3<<<(n + 255) / 256, 256>>>(n, e);
    k_scatter<<<(e + 255) / 256, 256>>>(ei, e);
    k_prep<<<256, 64>>>(wg, att_s, att_d, wc1, bc1, bg);

    int gs = 444;
    // GCN layer 1
    k_gcn_agg<<<(n + 7) / 8, 256>>>(b1, n, 0, 0);
    // GCN layer 2 (residual)
    k_gemm64<<<gs, 256>>>(w2, n);
    k_gcn_agg<<<(n + 7) / 8, 256>>>(b2, n, 1, 0);
    // GCN layer 3 (residual + fused attention coeffs + h16 copy)
    k_gemm64<<<gs, 256>>>(w3, n);
    k_gcn_agg<<<(n + 7) / 8, 256>>>(b3, n, 1, 1);
    // GAT aggregation (warp per node)
    k_gat_agg3<<<(n + 7) / 8, 256>>>(n);
    // classifier (wmma) — 82944 B dynamic smem
    static int smem_set = 0;
    if (!smem_set) {
        cudaFuncSetAttribute(k_classifier, cudaFuncAttributeMaxDynamicSharedMemorySize, 98304);
        smem_set = 1;
    }
    k_classifier<<<(n + 63) / 64, 256, 82944>>>(wc2, bc2, out, n);
}